// round 17
// baseline (speedup 1.0000x reference)
#include <cuda_runtime.h>
#include <cuda_fp16.h>

// PLE layers, round 17: R16 + three latency cuts.
//   1) one mbarrier per 4-chunk group (and per gate stack) instead of per chunk
//   2) all 6 LDSMs hoisted to chunk start (fb[16]) -> no mid-chunk MMA stall
//   3) gate GEMM split across all 16 warps (K-chunk split, deterministic
//      smem-partial reduction in softmax)

#define BT      16384
#define IN_D    256
#define EXP_D   128
#define TB      64
#define NTH     512
#define XS2     132         // half2 X stride (uints)
#define GSS     57
#define NGRP    48          // groups of 4 chunks (192 expert chunks)
#define CH_U    2048        // uints per chunk (8 KB)
#define CH_B    (CH_U*4)

// smem word offsets
#define OFF_XS   0                            // 64*132 = 8448 w
#define OFF_WS   8448                         // ring: 8 x 2048 w
#define OFF_WSM  (OFF_WS + 8*CH_U)            // 24832
#define OFF_BSM  (OFF_WSM + TB*GSS)           // 28480
#define OFF_MB   (OFF_BSM + 3*1024)           // 31552 (mbarriers)
#define OFF_GP   (OFF_MB + 32)                // 31584 gate partials [wn][r][n] 4*64*32
#define SMEM_WORDS (OFF_GP + 8192)            // 39776 w = 159,104 B

#define BSWZ(o) ((o) ^ (((o) >> 3) & 0x30))

__device__ __align__(128) unsigned Wc2[NGRP * 4 * CH_U];   // expert chunks
__device__ __align__(128) unsigned Gc2[24 * CH_U];         // gate chunks

__device__ __forceinline__ void bulk_cp(unsigned dst, const void* src, unsigned bytes,
                                        unsigned mbar) {
    asm volatile(
        "cp.async.bulk.shared::cta.global.mbarrier::complete_tx::bytes [%0], [%1], %2, [%3];"
        :: "r"(dst), "l"(src), "r"(bytes), "r"(mbar) : "memory");
}
#define MBAR_INIT(addr, cnt) \
    asm volatile("mbarrier.init.shared.b64 [%0], %1;" :: "r"(addr), "r"(cnt) : "memory")
#define MBAR_EXPECT_TX(addr, bytes) \
    asm volatile("mbarrier.arrive.expect_tx.shared.b64 _, [%0], %1;" \
                 :: "r"(addr), "r"((unsigned)(bytes)) : "memory")

__device__ __forceinline__ void mbar_wait(unsigned addr, unsigned parity) {
    unsigned done;
    asm volatile("{\n .reg .pred p;\n"
                 " mbarrier.try_wait.parity.acquire.cta.shared::cta.b64 p, [%1], %2;\n"
                 " selp.b32 %0, 1, 0, p;\n}"
                 : "=r"(done) : "r"(addr), "r"(parity) : "memory");
    if (!done) {
        asm volatile("{\n .reg .pred P1;\n"
                     "WL_%=:\n"
                     " mbarrier.try_wait.parity.acquire.cta.shared::cta.b64 P1, [%0], %1, 0x989680;\n"
                     " @P1 bra.uni WD_%=;\n"
                     " bra.uni WL_%=;\n"
                     "WD_%=:\n}"
                     :: "r"(addr), "r"(parity) : "memory");
    }
}

#define LDSM4(r0, r1, r2, r3, addr) \
    asm volatile("ldmatrix.sync.aligned.m8n8.x4.shared.b16 {%0,%1,%2,%3}, [%4];" \
                 : "=r"(r0), "=r"(r1), "=r"(r2), "=r"(r3) : "r"(addr))

// f32-accum HMMA (gate GEMM)
__device__ __forceinline__ void mma16(float& c0, float& c1, float& c2, float& c3,
                                      unsigned a0, unsigned a1, unsigned a2, unsigned a3,
                                      unsigned b0, unsigned b1) {
    asm volatile(
        "mma.sync.aligned.m16n8k16.row.col.f32.f16.f16.f32 "
        "{%0,%1,%2,%3}, {%4,%5,%6,%7}, {%8,%9}, {%0,%1,%2,%3};\n"
        : "+f"(c0), "+f"(c1), "+f"(c2), "+f"(c3)
        : "r"(a0), "r"(a1), "r"(a2), "r"(a3), "r"(b0), "r"(b1));
}
// f16-accum HMMA (expert GEMM)
__device__ __forceinline__ void mma16h(unsigned& d0, unsigned& d1,
                                       unsigned a0, unsigned a1, unsigned a2, unsigned a3,
                                       unsigned b0, unsigned b1) {
    asm volatile(
        "mma.sync.aligned.m16n8k16.row.col.f16.f16.f16.f16 "
        "{%0,%1}, {%2,%3,%4,%5}, {%6,%7}, {%0,%1};\n"
        : "+r"(d0), "+r"(d1)
        : "r"(a0), "r"(a1), "r"(a2), "r"(a3), "r"(b0), "r"(b1));
}

// ---- prepass: W[e][k][n] -> fp16x2 k-pairs, chunk images with baked swizzle ----
__global__ void w_convert2(const float* __restrict__ Wa, const float* __restrict__ Wb,
                           const float* __restrict__ Wsx) {
    int id = blockIdx.x * blockDim.x + threadIdx.x;
    int kp = id & 15;
    int n  = (id >> 4) & 127;
    int c  = (id >> 11) & 7;
    int e  = (id >> 14) & 7;
    int sg = id >> 17;
    const float* W = (sg == 0) ? Wa : (sg == 1) ? Wb : Wsx;
    int k = c * 32 + 2 * kp;
    const float* p = W + ((size_t)e * IN_D + k) * EXP_D + n;
    __half2 h = __floats2half2_rn(p[0], p[EXP_D]);
    unsigned o = (unsigned)(n * 64 + kp * 4);
    int chunk = (sg * 8 + e) * 8 + c;
    *(unsigned*)((char*)(Wc2 + (size_t)chunk * CH_U) + BSWZ(o)) = *(unsigned*)&h;
}

// ---- prepass: G[n][k] -> gate chunk images (rows >= NG zero-padded) ----
__global__ void g_convert(const float* __restrict__ Ga, const float* __restrict__ Gb,
                          const float* __restrict__ Gq) {
    int id = blockIdx.x * blockDim.x + threadIdx.x;   // 24*2048
    int kp = id & 15;
    int n  = (id >> 4) & 127;
    int c  = (id >> 11) & 7;
    int sg = id >> 14;
    const float* G = (sg == 0) ? Ga : (sg == 1) ? Gb : Gq;
    const int NG = (sg == 2) ? 24 : 16;
    __half2 h;
    if (n < NG) {
        const float* p = G + (size_t)n * IN_D + c * 32 + 2 * kp;
        h = __floats2half2_rn(p[0], p[1]);
    } else {
        h = __floats2half2_rn(0.f, 0.f);
    }
    unsigned o = (unsigned)(n * 64 + kp * 4);
    int chunk = sg * 8 + c;
    *(unsigned*)((char*)(Gc2 + (size_t)chunk * CH_U) + BSWZ(o)) = *(unsigned*)&h;
}

// ---------------- main fused kernel ----------------
__global__ __launch_bounds__(NTH, 1)
void ple_kernel(const float* __restrict__ xa, const float* __restrict__ xb,
                const float* __restrict__ xsh,
                const float* __restrict__ ba, const float* __restrict__ bb,
                const float* __restrict__ bsx,
                float* __restrict__ out)
{
    extern __shared__ float smem[];
    unsigned* xs2 = (unsigned*)(smem + OFF_XS);
    float*    wsm = smem + OFF_WSM;
    float*    bsm = smem + OFF_BSM;
    float*    gp  = smem + OFF_GP;            // gate partials [wn][r][n32]

    const int tid  = threadIdx.x;
    const int lane = tid & 31;
    const int wid  = tid >> 5;
    const int gid  = lane >> 2;
    const int tig  = lane & 3;
    const int wm   = wid >> 2;                // 0..3 (16-row band)
    const int wn   = wid & 3;                 // 0..3 (32-col band / gate K split)
    const int sub  = lane >> 3;
    const int l7   = lane & 7;
    const int row0 = blockIdx.x * TB;

    const unsigned xs2_u = (unsigned)__cvta_generic_to_shared(xs2);
    const unsigned ws_u  = (unsigned)__cvta_generic_to_shared(smem + OFF_WS);
    const unsigned mbA   = (unsigned)__cvta_generic_to_shared(smem + OFF_MB);  // 2 group barriers
    const unsigned mbG   = mbA + 16;                                           // gate barrier

    // ldmatrix lane base addresses
    unsigned addrA, addrB[2][2], addrGB[2][2];
    {
        int rowA = wm * 16 + (sub & 1) * 8 + l7;
        addrA = xs2_u + (rowA * XS2 + (sub >> 1) * 4) * 4;
    }
    #pragma unroll
    for (int ntp = 0; ntp < 2; ++ntp) {
        int rowB = wn * 32 + ntp * 16 + (sub >> 1) * 8 + l7;
        unsigned o0 = (unsigned)(rowB * 64 + (sub & 1) * 16);
        unsigned s0 = BSWZ(o0);
        addrB[ntp][0] = ws_u + s0;
        addrB[ntp][1] = ws_u + (s0 ^ 32);
        int rowG = ntp * 16 + (sub >> 1) * 8 + l7;        // gate: cols 0..31 always
        unsigned og = (unsigned)(rowG * 64 + (sub & 1) * 16);
        unsigned sg0 = BSWZ(og);
        addrGB[ntp][0] = ws_u + sg0;
        addrGB[ntp][1] = ws_u + (sg0 ^ 32);
    }

    auto issue_group = [&](int G) {           // 4 expert chunks -> half G&1, ONE barrier
        unsigned mb = mbA + (G & 1) * 8;
        MBAR_EXPECT_TX(mb, 4 * CH_B);
        #pragma unroll
        for (int i = 0; i < 4; ++i) {
            int Q = G * 4 + i;
            int s = ((G & 1) << 2) + i;
            bulk_cp(ws_u + s * CH_B, Wc2 + (size_t)Q * CH_U, CH_B, mb);
        }
    };

    auto stage_x = [&](const float* X) {
        const float4* src = (const float4*)(X + (size_t)row0 * IN_D);
        #pragma unroll
        for (int j = 0; j < 8; ++j) {
            int idx = tid + j * NTH;
            int r = idx >> 6, k4 = idx & 63;
            float4 v = __ldg(src + idx);
            __half2 h0 = __floats2half2_rn(v.x, v.y);
            __half2 h1 = __floats2half2_rn(v.z, v.w);
            uint2 u = { *(unsigned*)&h0, *(unsigned*)&h1 };
            *(uint2*)(xs2 + r * XS2 + 2 * k4) = u;
        }
    };

    if (tid == 0) {
        MBAR_INIT(mbA, 1);
        MBAR_INIT(mbA + 8, 1);
        MBAR_INIT(mbG, 1);
    }
    __syncthreads();

    for (int i = tid; i < 1024; i += NTH) {
        bsm[i]        = __ldg(ba + i);
        bsm[1024 + i] = __ldg(bb + i);
        bsm[2048 + i] = __ldg(bsx + i);
    }

    // ---------------- Phase 1: gate logits via HMMA (all 16 warps) + softmax -------
    #pragma unroll 1
    for (int sg = 0; sg < 3; ++sg) {
        __syncthreads();                       // prior xs2/ring readers done
        stage_x((sg == 0) ? xa : (sg == 1) ? xb : xsh);
        if (tid == 0) {                        // all 8 gate chunks, one barrier
            MBAR_EXPECT_TX(mbG, 8 * CH_B);
            #pragma unroll
            for (int c = 0; c < 8; ++c)
                bulk_cp(ws_u + c * CH_B, Gc2 + (size_t)(sg * 8 + c) * CH_U, CH_B, mbG);
        }
        __syncthreads();                       // X tile visible
        mbar_wait(mbG, sg & 1);

        // warp (wm,wn): rows wm band, K-chunks 2wn, 2wn+1, f32 accum
        float ge[4][4];
        #pragma unroll
        for (int nt = 0; nt < 4; ++nt)
            #pragma unroll
            for (int v = 0; v < 4; ++v) ge[nt][v] = 0.f;
        #pragma unroll
        for (int j = 0; j < 2; ++j) {
            const int c = 2 * wn + j;
            const unsigned sb = (unsigned)c * CH_B;
            unsigned fa0[4], fa1[4], fb[16];
            unsigned ka = (unsigned)(c * 64);
            LDSM4(fa0[0], fa0[1], fa0[2], fa0[3], addrA + ka);
            LDSM4(fa1[0], fa1[1], fa1[2], fa1[3], addrA + ka + 32);
            LDSM4(fb[0], fb[1], fb[2], fb[3], addrGB[0][0] + sb);
            LDSM4(fb[4], fb[5], fb[6], fb[7], addrGB[1][0] + sb);
            LDSM4(fb[8], fb[9], fb[10], fb[11], addrGB[0][1] + sb);
            LDSM4(fb[12], fb[13], fb[14], fb[15], addrGB[1][1] + sb);
            #pragma unroll
            for (int nt = 0; nt < 4; ++nt) {
                unsigned i0 = (nt >> 1) * 4 + (nt & 1) * 2;
                mma16(ge[nt][0], ge[nt][1], ge[nt][2], ge[nt][3],
                      fa0[0], fa0[1], fa0[2], fa0[3], fb[i0], fb[i0 + 1]);
                mma16(ge[nt][0], ge[nt][1], ge[nt][2], ge[nt][3],
                      fa1[0], fa1[1], fa1[2], fa1[3], fb[8 + i0], fb[8 + i0 + 1]);
            }
        }
        // write partials (all 32 cols, unguarded -> gp is scratch)
        {
            float* gpw = gp + wn * (TB * 32);
            int r0 = wm * 16 + gid;
            #pragma unroll
            for (int nt = 0; nt < 4; ++nt) {
                int n0 = nt * 8 + 2 * tig;
                gpw[r0 * 32 + n0]           = ge[nt][0];
                gpw[r0 * 32 + n0 + 1]       = ge[nt][1];
                gpw[(r0 + 8) * 32 + n0]     = ge[nt][2];
                gpw[(r0 + 8) * 32 + n0 + 1] = ge[nt][3];
            }
        }
        __syncthreads();
        if (sg == 2 && tid == 0) { issue_group(0); issue_group(1); }
        const int NG = (sg == 2) ? 24 : 16, WOFF = sg * 16;
        if (tid < TB) {                        // reduce partials + softmax
            float* wr = wsm + tid * GSS + WOFF;
            float m = -1e30f;
            for (int g = 0; g < NG; ++g) {
                float v = gp[tid * 32 + g] + gp[TB * 32 + tid * 32 + g]
                        + gp[2 * TB * 32 + tid * 32 + g] + gp[3 * TB * 32 + tid * 32 + g];
                wr[g] = v;
                m = fmaxf(m, v);
            }
            float s = 0.f;
            for (int g = 0; g < NG; ++g) { float e = expf(wr[g] - m); wr[g] = e; s += e; }
            float inv = 1.f / s;
            for (int g = 0; g < NG; ++g) wr[g] *= inv;
        }
    }

    // ---------------- Phase 2: fp16-accum expert GEMMs, group pipeline ----------
    float oa[4][4] = {}, ob[4][4] = {}, os[4][4] = {};
    float ec[4][4];

    #pragma unroll 1
    for (int g = 0; g < NGRP; ++g) {
        __syncthreads();                       // half (g+1)&1 free; group g-1 done
        if (tid == 0 && g >= 1 && g + 1 < NGRP) issue_group(g + 1);

        if ((g & 15) == 0) {                   // stack boundary: restage X
            const int sgk = g >> 4;
            stage_x((sgk == 0) ? xa : (sgk == 1) ? xb : xsh);
            __syncthreads();
        }

        mbar_wait(mbA + (g & 1) * 8, (g >> 1) & 1);   // whole group landed

        #pragma unroll
        for (int i = 0; i < 4; ++i) {
            const int Q = g * 4 + i;
            const int c = Q & 7;
            const unsigned sb = (unsigned)(((g & 1) << 2) + i) * CH_B;

            if (c == 0) {
                #pragma unroll
                for (int nt = 0; nt < 4; ++nt)
                    #pragma unroll
                    for (int v = 0; v < 4; ++v) ec[nt][v] = 0.f;
            }

            unsigned fa[8], fb[16];
            unsigned hc[4][2];
            #pragma unroll
            for (int nt = 0; nt < 4; ++nt) { hc[nt][0] = 0u; hc[nt][1] = 0u; }

            {   // all fragments up front: MMAs never stall mid-chunk
                unsigned ka = (unsigned)(c * 64);
                LDSM4(fa[0], fa[1], fa[2], fa[3], addrA + ka);
                LDSM4(fa[4], fa[5], fa[6], fa[7], addrA + ka + 32);
                LDSM4(fb[0], fb[1], fb[2], fb[3], addrB[0][0] + sb);
                LDSM4(fb[4], fb[5], fb[6], fb[7], addrB[1][0] + sb);
                LDSM4(fb[8], fb[9], fb[10], fb[11], addrB[0][1] + sb);
                LDSM4(fb[12], fb[13], fb[14], fb[15], addrB[1][1] + sb);
            }
            #pragma unroll
            for (int nt = 0; nt < 4; ++nt) {
                unsigned i0 = (nt >> 1) * 4 + (nt & 1) * 2;
                mma16h(hc[nt][0], hc[nt][1],
                       fa[0], fa[1], fa[2], fa[3], fb[i0], fb[i0 + 1]);
                mma16h(hc[nt][0], hc[nt][1],
                       fa[4], fa[5], fa[6], fa[7], fb[8 + i0], fb[8 + i0 + 1]);
            }
            #pragma unroll
            for (int nt = 0; nt < 4; ++nt) {   // promote K=32 fp16 partial
                __half2 hlo, hhi;
                *(unsigned*)&hlo = hc[nt][0];
                *(unsigned*)&hhi = hc[nt][1];
                float2 lo = __half22float2(hlo);
                float2 hi = __half22float2(hhi);
                ec[nt][0] += lo.x; ec[nt][1] += lo.y;
                ec[nt][2] += hi.x; ec[nt][3] += hi.y;
            }

            if (c == 7) {
                const int e = (Q >> 3) & 7;
                const int sgk = Q >> 6;
                int rl = wm * 16 + gid;
                float w1l, w1h, w2l, w2h, w3l = 0.f, w3h = 0.f;
                if (sgk == 0) {
                    w1l = wsm[rl * GSS + e];      w1h = wsm[(rl + 8) * GSS + e];
                    w2l = wsm[rl * GSS + 32 + e]; w2h = wsm[(rl + 8) * GSS + 32 + e];
                } else if (sgk == 1) {
                    w1l = wsm[rl * GSS + 16 + e]; w1h = wsm[(rl + 8) * GSS + 16 + e];
                    w2l = wsm[rl * GSS + 40 + e]; w2h = wsm[(rl + 8) * GSS + 40 + e];
                } else {
                    w1l = wsm[rl * GSS + 8 + e];  w1h = wsm[(rl + 8) * GSS + 8 + e];
                    w2l = wsm[rl * GSS + 24 + e]; w2h = wsm[(rl + 8) * GSS + 24 + e];
                    w3l = wsm[rl * GSS + 48 + e]; w3h = wsm[(rl + 8) * GSS + 48 + e];
                }
                #pragma unroll
                for (int nt = 0; nt < 4; ++nt) {
                    int c0 = wn * 32 + nt * 8 + 2 * tig;
                    const float* bp = bsm + sgk * 1024 + e * EXP_D + c0;
                    float t0 = ec[nt][0] + bp[0];
                    float t1 = ec[nt][1] + bp[1];
                    float t2 = ec[nt][2] + bp[0];
                    float t3 = ec[nt][3] + bp[1];
                    if (sgk == 0) {
                        oa[nt][0] += w1l * t0; oa[nt][1] += w1l * t1;
                        oa[nt][2] += w1h * t2; oa[nt][3] += w1h * t3;
                        os[nt][0] += w2l * t0; os[nt][1] += w2l * t1;
                        os[nt][2] += w2h * t2; os[nt][3] += w2h * t3;
                    } else if (sgk == 1) {
                        ob[nt][0] += w1l * t0; ob[nt][1] += w1l * t1;
                        ob[nt][2] += w1h * t2; ob[nt][3] += w1h * t3;
                        os[nt][0] += w2l * t0; os[nt][1] += w2l * t1;
                        os[nt][2] += w2h * t2; os[nt][3] += w2h * t3;
                    } else {
                        oa[nt][0] += w1l * t0; oa[nt][1] += w1l * t1;
                        oa[nt][2] += w1h * t2; oa[nt][3] += w1h * t3;
                        ob[nt][0] += w2l * t0; ob[nt][1] += w2l * t1;
                        ob[nt][2] += w2h * t2; ob[nt][3] += w2h * t3;
                        os[nt][0] += w3l * t0; os[nt][1] += w3l * t1;
                        os[nt][2] += w3h * t2; os[nt][3] += w3h * t3;
                    }
                }
            }
        }
    }

    // ---------------- write out: [out_a | out_b | out_s], each [B,128] ----------------
    const size_t OS = (size_t)BT * EXP_D;
    {
        int r = row0 + wm * 16 + gid;
        #pragma unroll
        for (int nt = 0; nt < 4; ++nt) {
            int c0 = wn * 32 + nt * 8 + 2 * tig;
            size_t p0 = (size_t)r * EXP_D + c0;
            size_t p1 = (size_t)(r + 8) * EXP_D + c0;
            *(float2*)(out + p0)          = make_float2(oa[nt][0], oa[nt][1]);
            *(float2*)(out + p1)          = make_float2(oa[nt][2], oa[nt][3]);
            *(float2*)(out + OS + p0)     = make_float2(ob[nt][0], ob[nt][1]);
            *(float2*)(out + OS + p1)     = make_float2(ob[nt][2], ob[nt][3]);
            *(float2*)(out + 2 * OS + p0) = make_float2(os[nt][0], os[nt][1]);
            *(float2*)(out + 2 * OS + p1) = make_float2(os[nt][2], os[nt][3]);
        }
    }
}

extern "C" void kernel_launch(void* const* d_in, const int* in_sizes, int n_in,
                              void* d_out, int out_size) {
    (void)in_sizes; (void)n_in; (void)out_size;

    w_convert2<<<1536, 256>>>((const float*)d_in[3], (const float*)d_in[5],
                              (const float*)d_in[7]);
    g_convert<<<192, 256>>>((const float*)d_in[9], (const float*)d_in[10],
                            (const float*)d_in[11]);

    constexpr int SMEM_BYTES = SMEM_WORDS * 4;   // 159,104 B
    cudaFuncSetAttribute(ple_kernel, cudaFuncAttributeMaxDynamicSharedMemorySize, SMEM_BYTES);
    ple_kernel<<<BT / TB, NTH, SMEM_BYTES>>>(
        (const float*)d_in[0], (const float*)d_in[1], (const float*)d_in[2],
        (const float*)d_in[4], (const float*)d_in[6], (const float*)d_in[8],
        (float*)d_out);
}